// round 15
// baseline (speedup 1.0000x reference)
#include <cuda_runtime.h>

// GatedCNNLayer: X (16,4096,1024) f32, G (1024,2) f32, Gb (2,) f32
// out[b,p,:] = X[b,2p,:]*g0 + X[b,2p+2,:]*g1,
//   g = softmax(X[b,2p+1,:] @ G + Gb), p in [0,2047)
//
// FINAL kernel — warp-per-pair, best of 14 tested variants; reproduced at
// 61.9us wall (3x) / 56.2-56.6us ncu / 78% DRAM.
//
// Design: one warp owns one (b,p): 32 lanes x 8 float4 = 1024 columns.
//  - All 24 LDG.128 (mid+left+right rows) front-batched before any dependent
//    math -> deep MLP window covers the gate-reduce latency.
//  - Gate reduce is warp-shuffle-only: zero block barriers in steady state.
//  - G (8KB) staged to smem once per block; Gb via __ldg.
//  - __ldcs on read-once mid rows, __stcs on the output stream, keeping L2
//    free for the even-row (left/right) within-replay dedup.
//  - 2-way softmax as overflow-safe sigmoid: 1/(1+exp(s1-s0)).
//
// Roofline: 384MB irreducible DRAM traffic (256MB read + 128MB write) at
// ~6.2TB/s achieved mixed-stream BW (chip ceiling, never exceeded by any of
// 10 schedules) = 62us — exactly the reproduced wall time. At the roofline.
// Falsified alternatives: pair-chaining, block-per-pair, 2-phase blend,
// persistent grid, 512-thread CTAs, gate/blend kernel split, L2 evict_last
// (v8 + createpolicy), 256-bit loads, two-pairs-per-warp.

#define BATCH 16
#define SEQ   4096
#define DIM   1024
#define D4    (DIM / 4)      // 256 float4 per row
#define PAIRS 2047
#define WPB   8              // warps per block
#define NBLKX ((PAIRS + WPB - 1) / WPB)   // 256

__global__ __launch_bounds__(256)
void gated_cnn_warp_kernel(const float* __restrict__ X,
                           const float* __restrict__ G,
                           const float* __restrict__ Gb,
                           float* __restrict__ out)
{
    __shared__ float4 Gsh[2 * D4];   // 8 KB, (d,2) interleaved as float4 pairs

    const int t    = threadIdx.x;
    const int warp = t >> 5;
    const int lane = t & 31;

    // Stage G once per block (cold path, single barrier)
    {
        const float4* __restrict__ G4 = (const float4*)G;
        Gsh[t]       = G4[t];
        Gsh[t + 256] = G4[t + 256];
    }
    __syncthreads();

    const int p = blockIdx.x * WPB + warp;
    if (p >= PAIRS) return;
    const int b = blockIdx.y;

    const float4* __restrict__ X4 = (const float4*)X;
    float4* __restrict__ O4 = (float4*)out;

    const size_t rowL = ((size_t)b * SEQ + (size_t)(2 * p)) * D4;   // f4 units
    const size_t rowM = rowL + D4;
    const size_t rowR = rowM + D4;

    // ---- front-batched loads: 8 mid + 8 left + 8 right LDG.128 ----
    float4 M[8], L[8], R[8];
    #pragma unroll
    for (int j = 0; j < 8; j++) M[j] = __ldcs(&X4[rowM + j * 32 + lane]);
    #pragma unroll
    for (int j = 0; j < 8; j++) L[j] = X4[rowL + j * 32 + lane];
    #pragma unroll
    for (int j = 0; j < 8; j++) R[j] = X4[rowR + j * 32 + lane];

    // ---- gate logits from mids (smem-resident G) ----
    float s0 = 0.f, s1 = 0.f;
    #pragma unroll
    for (int j = 0; j < 8; j++) {
        const int idx = j * 32 + lane;
        const float4 m  = M[j];
        const float4 ga = Gsh[2 * idx];
        const float4 gc = Gsh[2 * idx + 1];
        s0 += m.x * ga.x + m.y * ga.z + m.z * gc.x + m.w * gc.z;
        s1 += m.x * ga.y + m.y * ga.w + m.z * gc.y + m.w * gc.w;
    }

    // ---- warp-only reduction (no block barrier) ----
    #pragma unroll
    for (int off = 16; off > 0; off >>= 1) {
        s0 += __shfl_xor_sync(0xFFFFFFFFu, s0, off);
        s1 += __shfl_xor_sync(0xFFFFFFFFu, s1, off);
    }
    s0 += __ldg(&Gb[0]);
    s1 += __ldg(&Gb[1]);

    // softmax over 2 logits: overflow-safe sigmoid form
    const float g0 = 1.0f / (1.0f + __expf(s1 - s0));
    const float g1 = 1.0f - g0;

    // ---- blend + streaming stores ----
    const size_t rowO = ((size_t)b * PAIRS + (size_t)p) * D4;
    #pragma unroll
    for (int j = 0; j < 8; j++) {
        float4 o;
        o.x = L[j].x * g0 + R[j].x * g1;
        o.y = L[j].y * g0 + R[j].y * g1;
        o.z = L[j].z * g0 + R[j].z * g1;
        o.w = L[j].w * g0 + R[j].w * g1;
        __stcs(&O4[rowO + j * 32 + lane], o);
    }
}

extern "C" void kernel_launch(void* const* d_in, const int* in_sizes, int n_in,
                              void* d_out, int out_size)
{
    const float* X  = (const float*)d_in[0];
    const float* G  = (const float*)d_in[1];
    const float* Gb = (const float*)d_in[2];
    float* out = (float*)d_out;

    dim3 grid(NBLKX, BATCH);
    gated_cnn_warp_kernel<<<grid, 256>>>(X, G, Gb, out);
}